// round 4
// baseline (speedup 1.0000x reference)
#include <cuda_runtime.h>
#include <math.h>

#define NN 50000
#define EE 800000
#define HIDD 128
#define CLSS 64
#define ATT 16

// ---------------- scratch (static device globals; no allocation) ----------------
__device__ float g_xw_a[NN * HIDD];      // dinva[src] * (X @ W)
__device__ float g_xw_l[NN * HIDD];      // dinvl[src] * (Y @ Wl)
__device__ float g_xbuf[NN * HIDD];
__device__ float g_ybuf[NN * CLSS];
__device__ int   g_counts[NN];
__device__ int   g_off[NN + 1];
__device__ int   g_cursor[NN];
__device__ int   g_bsum[64];
__device__ int   g_csr_src[EE];
__device__ float g_csr_w0[EE];
__device__ float g_csr_w1[EE];
__device__ float g_dinva[NN];
__device__ float g_dinvl0[NN];
__device__ float g_dinvl1[NN];
__device__ float g_degl0[NN];
__device__ float g_degl1[NN];

// ---------------- setup: histogram + degrees ----------------
__global__ void hist_init_k(int* counts, float* degl0, float* degl1, int n) {
    int i = blockIdx.x * blockDim.x + threadIdx.x;
    if (i < n) { counts[i] = 0; degl0[i] = 1.f; degl1[i] = 1.f; }  // self-loop w=1
}

__global__ void hist_k(const int* __restrict__ col,
                       const float* __restrict__ ew0, const float* __restrict__ ew1,
                       int* counts, float* degl0, float* degl1, int e) {
    int i = blockIdx.x * blockDim.x + threadIdx.x;
    if (i < e) {
        int c = col[i];
        atomicAdd(&counts[c], 1);
        atomicAdd(&degl0[c], ew0[i]);
        atomicAdd(&degl1[c], ew1[i]);
    }
}

__global__ void dinv_k(const int* __restrict__ counts,
                       const float* __restrict__ degl0, const float* __restrict__ degl1,
                       float* dinva, float* dinvl0, float* dinvl1, int n) {
    int i = blockIdx.x * blockDim.x + threadIdx.x;
    if (i < n) {
        dinva[i]  = rsqrtf(1.f + (float)counts[i]);
        dinvl0[i] = rsqrtf(degl0[i]);
        dinvl1[i] = rsqrtf(degl1[i]);
    }
}

// ---------------- parallel exclusive scan (3 kernels) ----------------
__global__ void scan_partials_k(const int* __restrict__ counts, int* bsum, int n) {
    int i = blockIdx.x * 1024 + threadIdx.x;
    int v = (i < n) ? counts[i] : 0;
#pragma unroll
    for (int o = 16; o > 0; o >>= 1) v += __shfl_xor_sync(0xffffffffu, v, o);
    __shared__ int ws[32];
    if ((threadIdx.x & 31) == 0) ws[threadIdx.x >> 5] = v;
    __syncthreads();
    if (threadIdx.x < 32) {
        int s = ws[threadIdx.x];
#pragma unroll
        for (int o = 16; o > 0; o >>= 1) s += __shfl_xor_sync(0xffffffffu, s, o);
        if (threadIdx.x == 0) bsum[blockIdx.x] = s;
    }
}

__global__ void scan_bsums_k(int* bsum, int* off_last, int nb) {
    if (threadIdx.x == 0) {
        int acc = 0;
        for (int i = 0; i < nb; i++) { int t = bsum[i]; bsum[i] = acc; acc += t; }
        *off_last = acc;
    }
}

__global__ void scan_final_k(const int* __restrict__ counts, const int* __restrict__ bsum,
                             int* off, int* cursor, int n) {
    int i = blockIdx.x * 1024 + threadIdx.x;
    int v = (i < n) ? counts[i] : 0;
    int lane = threadIdx.x & 31, wid = threadIdx.x >> 5;
    int inc = v;
#pragma unroll
    for (int o = 1; o < 32; o <<= 1) {
        int t = __shfl_up_sync(0xffffffffu, inc, o);
        if (lane >= o) inc += t;
    }
    __shared__ int ws[32];
    if (lane == 31) ws[wid] = inc;
    __syncthreads();
    if (wid == 0) {
        int s = ws[lane];
        int si = s;
#pragma unroll
        for (int o = 1; o < 32; o <<= 1) {
            int t = __shfl_up_sync(0xffffffffu, si, o);
            if (lane >= o) si += t;
        }
        ws[lane] = si - s;  // exclusive warp offsets
    }
    __syncthreads();
    int excl = inc - v + ws[wid] + bsum[blockIdx.x];
    if (i < n) { off[i] = excl; cursor[i] = excl; }
}

__global__ void csr_scatter_k(const int* __restrict__ row, const int* __restrict__ col,
                              const float* __restrict__ ew0, const float* __restrict__ ew1,
                              int* cursor, int* csr_src, float* csr_w0, float* csr_w1, int e) {
    int i = blockIdx.x * blockDim.x + threadIdx.x;
    if (i < e) {
        int c = col[i];
        int p = atomicAdd(&cursor[c], 1);
        csr_src[p] = row[i];
        csr_w0[p] = ew0[i];
        csr_w1[p] = ew1[i];
    }
}

// ---------------- register-tiled GEMM with packed fp32x2 FMA ----------------
// out[n, NOUT] = X[n, K] @ W[K, NOUT]; epilogue:
//   MODE 0: out[r, :] = acc * sb[r]       (per-row dinv scale)
//   MODE 1: out[r, c] = sigmoid(acc + sb[c])
// Block: BM=64 rows x NOUT cols. Thread micro-tile: TM=8 x TN=4.
// k is processed in pairs via fma.rn.f32x2 (FFMA2 — PTX-only, 2x fp32 FMA rate).
template <int K, int NOUT, int MODE>
__global__ void __launch_bounds__(NOUT / 4 * 8)
gemm_t(const float* __restrict__ X, const float* __restrict__ W,
       const float* __restrict__ sb, float* __restrict__ out, int n) {
    constexpr int BM = 64;
    constexpr int TM = 8;
    constexpr int TN = 4;
    constexpr int TX = NOUT / TN;          // 32 or 16
    constexpr int NT = TX * (BM / TM);     // 256 or 128
    __shared__ float sX[BM * K];
    int row0 = blockIdx.x * BM;

    // load X tile (coalesced float4)
    for (int idx = threadIdx.x; idx < BM * (K / 4); idx += NT) {
        int r = idx / (K / 4), kq = idx % (K / 4);
        int gr = row0 + r;
        float4 v = (gr < n) ? __ldg(&((const float4*)X)[(size_t)gr * (K / 4) + kq])
                            : make_float4(0.f, 0.f, 0.f, 0.f);
        *(float4*)&sX[r * K + kq * 4] = v;
    }
    __syncthreads();

    int tx = threadIdx.x % TX;   // column group
    int ty = threadIdx.x / TX;   // row group
    const float* xrow = &sX[ty * TM * K];

    unsigned long long acc2[TM][TN];
#pragma unroll
    for (int m = 0; m < TM; m++)
#pragma unroll
        for (int c = 0; c < TN; c++) acc2[m][c] = 0ull;

#pragma unroll 2
    for (int kp = 0; kp < K / 2; kp++) {
        float4 w0 = __ldg((const float4*)&W[(size_t)(2 * kp) * NOUT + tx * TN]);
        float4 w1 = __ldg((const float4*)&W[(size_t)(2 * kp + 1) * NOUT + tx * TN]);
        unsigned long long wp[TN];
        asm("mov.b64 %0, {%1, %2};" : "=l"(wp[0]) : "f"(w0.x), "f"(w1.x));
        asm("mov.b64 %0, {%1, %2};" : "=l"(wp[1]) : "f"(w0.y), "f"(w1.y));
        asm("mov.b64 %0, {%1, %2};" : "=l"(wp[2]) : "f"(w0.z), "f"(w1.z));
        asm("mov.b64 %0, {%1, %2};" : "=l"(wp[3]) : "f"(w0.w), "f"(w1.w));
        unsigned long long ap[TM];
#pragma unroll
        for (int m = 0; m < TM; m++)
            ap[m] = *(const unsigned long long*)&xrow[m * K + 2 * kp];
#pragma unroll
        for (int m = 0; m < TM; m++) {
#pragma unroll
            for (int c = 0; c < TN; c++)
                asm("fma.rn.f32x2 %0, %1, %2, %0;"
                    : "+l"(acc2[m][c]) : "l"(ap[m]), "l"(wp[c]));
        }
    }

#pragma unroll
    for (int m = 0; m < TM; m++) {
        int gr = row0 + ty * TM + m;
        if (gr < n) {
            float s[TN];
#pragma unroll
            for (int c = 0; c < TN; c++) {
                float lo, hi;
                asm("mov.b64 {%0, %1}, %2;" : "=f"(lo), "=f"(hi) : "l"(acc2[m][c]));
                s[c] = lo + hi;
            }
            float4 o;
            if (MODE == 0) {
                float sc = __ldg(&sb[gr]);
                o = make_float4(s[0] * sc, s[1] * sc, s[2] * sc, s[3] * sc);
            } else {
                float4 b = __ldg((const float4*)&sb[tx * TN]);
                o.x = 1.f / (1.f + expf(-(s[0] + b.x)));
                o.y = 1.f / (1.f + expf(-(s[1] + b.y)));
                o.z = 1.f / (1.f + expf(-(s[2] + b.z)));
                o.w = 1.f / (1.f + expf(-(s[3] + b.w)));
            }
            *(float4*)&out[(size_t)gr * NOUT + tx * TN] = o;
        }
    }
}

// ---------------- fused gather + attention: warp per node ----------------
__global__ void gather_fuse_k(const float4* __restrict__ xwa, const float4* __restrict__ xwl,
                              const int* __restrict__ off, const int* __restrict__ csr_src,
                              const float* __restrict__ csr_w,
                              const float* __restrict__ dinva, const float* __restrict__ dinvl,
                              const float* __restrict__ b_adj, const float* __restrict__ b_lab,
                              const float* __restrict__ ap1, const float* __restrict__ apb1,
                              const float* __restrict__ ap2,
                              float4* __restrict__ xout, int do_relu, int n) {
    __shared__ float s_ap1t[ATT * HIDD];  // transposed: [j][feature]
    __shared__ float s_b[ATT], s_a2[ATT];
    for (int idx = threadIdx.x; idx < ATT * HIDD; idx += blockDim.x) {
        int j = idx >> 7, k = idx & 127;
        s_ap1t[idx] = ap1[k * ATT + j];
    }
    if (threadIdx.x < ATT) {
        s_b[threadIdx.x]  = apb1[threadIdx.x];
        s_a2[threadIdx.x] = ap2[threadIdx.x];
    }
    __syncthreads();

    int gt = blockIdx.x * blockDim.x + threadIdx.x;
    int node = gt >> 5;
    if (node >= n) return;
    int lane = threadIdx.x & 31;

    // self-loop contribution (weight 1 in both convs)
    float4 acc_a = __ldg(&xwa[node * 32 + lane]);
    float4 acc_l = __ldg(&xwl[node * 32 + lane]);

    int start = __ldg(&off[node]);
    int end   = __ldg(&off[node + 1]);
    int j = start;
    for (; j + 32 <= end; j += 32) {
        int rr0   = __ldg(&csr_src[j + lane]);
        float ww0 = __ldg(&csr_w[j + lane]);
#pragma unroll 8
        for (int i = 0; i < 32; i++) {
            int rr  = __shfl_sync(0xffffffffu, rr0, i);
            float w = __shfl_sync(0xffffffffu, ww0, i);
            float4 va = __ldg(&xwa[rr * 32 + lane]);
            float4 vl = __ldg(&xwl[rr * 32 + lane]);
            acc_a.x += va.x; acc_a.y += va.y; acc_a.z += va.z; acc_a.w += va.w;
            acc_l.x = fmaf(w, vl.x, acc_l.x);
            acc_l.y = fmaf(w, vl.y, acc_l.y);
            acc_l.z = fmaf(w, vl.z, acc_l.z);
            acc_l.w = fmaf(w, vl.w, acc_l.w);
        }
    }
    if (j < end) {
        int m = end - j;
        int rr0   = (lane < m) ? __ldg(&csr_src[j + lane]) : 0;
        float ww0 = (lane < m) ? __ldg(&csr_w[j + lane]) : 0.f;
#pragma unroll 4
        for (int i = 0; i < m; i++) {
            int rr  = __shfl_sync(0xffffffffu, rr0, i);
            float w = __shfl_sync(0xffffffffu, ww0, i);
            float4 va = __ldg(&xwa[rr * 32 + lane]);
            float4 vl = __ldg(&xwl[rr * 32 + lane]);
            acc_a.x += va.x; acc_a.y += va.y; acc_a.z += va.z; acc_a.w += va.w;
            acc_l.x = fmaf(w, vl.x, acc_l.x);
            acc_l.y = fmaf(w, vl.y, acc_l.y);
            acc_l.z = fmaf(w, vl.z, acc_l.z);
            acc_l.w = fmaf(w, vl.w, acc_l.w);
        }
    }

    // finalize conv outputs: z = dinv[dst] * acc + bias
    float da = __ldg(&dinva[node]);
    float dl = __ldg(&dinvl[node]);
    float4 ba4 = __ldg(&((const float4*)b_adj)[lane]);
    float4 bl4 = __ldg(&((const float4*)b_lab)[lane]);
    float z0[4], z1[4];
    z0[0] = fmaf(da, acc_a.x, ba4.x); z0[1] = fmaf(da, acc_a.y, ba4.y);
    z0[2] = fmaf(da, acc_a.z, ba4.z); z0[3] = fmaf(da, acc_a.w, ba4.w);
    z1[0] = fmaf(dl, acc_l.x, bl4.x); z1[1] = fmaf(dl, acc_l.y, bl4.y);
    z1[2] = fmaf(dl, acc_l.z, bl4.z); z1[3] = fmaf(dl, acc_l.w, bl4.w);

    // attention over the 2 views; lane owns features [4*lane, 4*lane+4)
    float w0 = 0.f, w1 = 0.f;
    const float4* ap1t4 = (const float4*)s_ap1t;
#pragma unroll
    for (int jj = 0; jj < ATT; jj++) {
        float4 a = ap1t4[jj * 32 + lane];
        float p0 = z0[0] * a.x + z0[1] * a.y + z0[2] * a.z + z0[3] * a.w;
        float p1 = z1[0] * a.x + z1[1] * a.y + z1[2] * a.z + z1[3] * a.w;
#pragma unroll
        for (int o = 16; o > 0; o >>= 1) {
            p0 += __shfl_xor_sync(0xffffffffu, p0, o);
            p1 += __shfl_xor_sync(0xffffffffu, p1, o);
        }
        w0 = fmaf(tanhf(p0 + s_b[jj]), s_a2[jj], w0);
        w1 = fmaf(tanhf(p1 + s_b[jj]), s_a2[jj], w1);
    }
    float beta0 = 1.f / (1.f + expf(w1 - w0));  // softmax over 2 views
    float beta1 = 1.f - beta0;

    float4 o4;
    o4.x = beta0 * z0[0] + beta1 * z1[0];
    o4.y = beta0 * z0[1] + beta1 * z1[1];
    o4.z = beta0 * z0[2] + beta1 * z1[2];
    o4.w = beta0 * z0[3] + beta1 * z1[3];
    if (do_relu) {
        o4.x = fmaxf(o4.x, 0.f); o4.y = fmaxf(o4.y, 0.f);
        o4.z = fmaxf(o4.z, 0.f); o4.w = fmaxf(o4.w, 0.f);
    }
    xout[node * 32 + lane] = o4;
}

// ---------------- host orchestration ----------------
extern "C" void kernel_launch(void* const* d_in, const int* in_sizes, int n_in,
                              void* d_out, int out_size) {
    const float* x_in  = (const float*)d_in[0];
    const float* y_in  = (const float*)d_in[1];
    const int*   row   = (const int*)d_in[2];
    const int*   col   = (const int*)d_in[3];
    const float* ews   = (const float*)d_in[4];  // [2, E]
    const float* W0    = (const float*)d_in[5];
    const float* b0    = (const float*)d_in[6];
    const float* W1    = (const float*)d_in[7];
    const float* b1    = (const float*)d_in[8];
    const float* Wl    = (const float*)d_in[9];
    const float* bl    = (const float*)d_in[10];
    const float* ap1   = (const float*)d_in[11];
    const float* apb1  = (const float*)d_in[12];
    const float* ap2   = (const float*)d_in[13];
    const float* mW    = (const float*)d_in[14];
    const float* mb    = (const float*)d_in[15];
    float* out = (float*)d_out;

    float *xw_a, *xw_l, *xbuf, *ybuf;
    float *dinva, *dinvl0, *dinvl1, *degl0, *degl1, *csr_w0, *csr_w1;
    int *counts, *off, *cursor, *csr_src, *bsum;
    cudaGetSymbolAddress((void**)&xw_a,   g_xw_a);
    cudaGetSymbolAddress((void**)&xw_l,   g_xw_l);
    cudaGetSymbolAddress((void**)&xbuf,   g_xbuf);
    cudaGetSymbolAddress((void**)&ybuf,   g_ybuf);
    cudaGetSymbolAddress((void**)&counts, g_counts);
    cudaGetSymbolAddress((void**)&off,    g_off);
    cudaGetSymbolAddress((void**)&cursor, g_cursor);
    cudaGetSymbolAddress((void**)&bsum,   g_bsum);
    cudaGetSymbolAddress((void**)&csr_src, g_csr_src);
    cudaGetSymbolAddress((void**)&csr_w0, g_csr_w0);
    cudaGetSymbolAddress((void**)&csr_w1, g_csr_w1);
    cudaGetSymbolAddress((void**)&dinva,  g_dinva);
    cudaGetSymbolAddress((void**)&dinvl0, g_dinvl0);
    cudaGetSymbolAddress((void**)&dinvl1, g_dinvl1);
    cudaGetSymbolAddress((void**)&degl0,  g_degl0);
    cudaGetSymbolAddress((void**)&degl1,  g_degl1);

    const float* ew0 = ews;
    const float* ew1 = ews + EE;

    const int n_blocks   = (NN + 255) / 256;
    const int e_blocks   = (EE + 255) / 256;
    const int scan_blk   = (NN + 1023) / 1024;   // 49
    const int gemm_blk   = (NN + 63) / 64;       // 782
    const int gf_blocks  = (NN * 32 + 255) / 256;

    // ---- CSR build (parallel scan) ----
    hist_init_k<<<n_blocks, 256>>>(counts, degl0, degl1, NN);
    hist_k<<<e_blocks, 256>>>(col, ew0, ew1, counts, degl0, degl1, EE);
    dinv_k<<<n_blocks, 256>>>(counts, degl0, degl1, dinva, dinvl0, dinvl1, NN);
    scan_partials_k<<<scan_blk, 1024>>>(counts, bsum, NN);
    scan_bsums_k<<<1, 32>>>(bsum, off + NN, scan_blk);
    scan_final_k<<<scan_blk, 1024>>>(counts, bsum, off, cursor, NN);
    csr_scatter_k<<<e_blocks, 256>>>(row, col, ew0, ew1, cursor,
                                     csr_src, csr_w0, csr_w1, EE);

    const float* convW[2] = {W0, W1};
    const float* convB[2] = {b0, b1};
    const float* dinvl[2] = {dinvl0, dinvl1};
    const float* csrw[2]  = {csr_w0, csr_w1};

    for (int layer = 0; layer < 2; layer++) {
        const float* Xin = (layer == 0) ? x_in : xbuf;
        const float* Yin = (layer == 0) ? y_in : ybuf;
        int last = (layer == 1);
        float* xout = last ? out : xbuf;
        float* yout = last ? (out + (size_t)NN * HIDD) : ybuf;

        gemm_t<HIDD, HIDD, 0><<<gemm_blk, 256>>>(Xin, convW[layer], dinva, xw_a, NN);
        gemm_t<CLSS, HIDD, 0><<<gemm_blk, 256>>>(Yin, Wl, dinvl[layer], xw_l, NN);

        gather_fuse_k<<<gf_blocks, 256>>>((const float4*)xw_a, (const float4*)xw_l,
                                          off, csr_src, csrw[layer],
                                          dinva, dinvl[layer],
                                          convB[layer], bl, ap1, apb1, ap2,
                                          (float4*)xout, last ? 0 : 1, NN);

        gemm_t<HIDD, CLSS, 1><<<gemm_blk, 128>>>(xout, mW, mb, yout, NN);
    }
}

// round 6
// speedup vs baseline: 1.2689x; 1.2689x over previous
#include <cuda_runtime.h>
#include <cuda_bf16.h>
#include <math.h>
#include <stdint.h>

#define NN 50000
#define EE 800000
#define HIDD 128
#define CLSS 64
#define ATT 16

// ---------------- scratch (static device globals; no allocation) ----------------
__device__ float g_xw_a[NN * HIDD];
__device__ float g_xw_l[NN * HIDD];
__device__ float g_xbuf[NN * HIDD];
__device__ float g_ybuf[NN * CLSS];
__device__ int   g_counts[NN];
__device__ int   g_off[NN + 1];
__device__ int   g_cursor[NN];
__device__ int   g_bsum[64];
__device__ int   g_csr_src[EE];
__device__ float g_csr_w0[EE];
__device__ float g_csr_w1[EE];
__device__ float g_dinva[NN];
__device__ float g_dinvl0[NN];
__device__ float g_dinvl1[NN];
__device__ float g_degl0[NN];
__device__ float g_degl1[NN];
// pre-split, pre-transposed weights: Wt[n][k] hi/lo, row stride K+8
__device__ __align__(16) __nv_bfloat16 g_w0hi[HIDD * (HIDD + 8)];
__device__ __align__(16) __nv_bfloat16 g_w0lo[HIDD * (HIDD + 8)];
__device__ __align__(16) __nv_bfloat16 g_w1hi[HIDD * (HIDD + 8)];
__device__ __align__(16) __nv_bfloat16 g_w1lo[HIDD * (HIDD + 8)];
__device__ __align__(16) __nv_bfloat16 g_wlhi[HIDD * (CLSS + 8)];
__device__ __align__(16) __nv_bfloat16 g_wllo[HIDD * (CLSS + 8)];
__device__ __align__(16) __nv_bfloat16 g_mwhi[CLSS * (HIDD + 8)];
__device__ __align__(16) __nv_bfloat16 g_mwlo[CLSS * (HIDD + 8)];

// ---------------- bf16 MMA helper (m16n8k16, fp32 acc) ----------------
__device__ __forceinline__ void mma16816(float* c, uint32_t a0, uint32_t a1, uint32_t a2,
                                         uint32_t a3, uint32_t b0, uint32_t b1) {
    asm volatile(
        "mma.sync.aligned.m16n8k16.row.col.f32.bf16.bf16.f32 "
        "{%0,%1,%2,%3}, {%4,%5,%6,%7}, {%8,%9}, {%0,%1,%2,%3};"
        : "+f"(c[0]), "+f"(c[1]), "+f"(c[2]), "+f"(c[3])
        : "r"(a0), "r"(a1), "r"(a2), "r"(a3), "r"(b0), "r"(b1));
}

// ---------------- W pre-split + transpose: W[K,NOUT] -> Wt[n][k] hi/lo ----------------
__global__ void wsplit_k(const float* __restrict__ W, __nv_bfloat16* hi, __nv_bfloat16* lo,
                         int K, int NOUT) {
    int idx = blockIdx.x * blockDim.x + threadIdx.x;
    if (idx >= K * NOUT) return;
    int k = idx / NOUT;
    int nn = idx % NOUT;
    float v = W[idx];
    __nv_bfloat16 h = __float2bfloat16(v);
    __nv_bfloat16 l = __float2bfloat16(v - __bfloat162float(h));
    int p = nn * (K + 8) + k;
    hi[p] = h;
    lo[p] = l;
}

// ---------------- MMA GEMM: out[n, NOUT] = X[n, K] @ W[K, NOUT] ----------------
// hi/lo split bf16, 3-term, fp32 accumulate.
//   MODE 0: out[r, :] = acc * sb[r]
//   MODE 1: out[r, c] = sigmoid(acc + sb[c])
template <int K, int NOUT, int MODE>
__global__ void __launch_bounds__(256, 1)
mma_gemm(const float* __restrict__ X,
         const __nv_bfloat16* __restrict__ Wthi, const __nv_bfloat16* __restrict__ Wtlo,
         const float* __restrict__ sb, float* __restrict__ out, int n) {
    constexpr int LD = K + 8;
    constexpr int NCB = NOUT / 8;
    extern __shared__ __nv_bfloat16 sm[];
    __nv_bfloat16* sAhi = sm;
    __nv_bfloat16* sAlo = sAhi + 128 * LD;
    __nv_bfloat16* sWhi = sAlo + 128 * LD;
    __nv_bfloat16* sWlo = sWhi + NOUT * LD;

    const int tid = threadIdx.x;
    const int row0 = blockIdx.x * 128;

    // copy pre-transposed W tiles (raw float4)
    {
        const float4* srch = (const float4*)Wthi;
        const float4* srcl = (const float4*)Wtlo;
        float4* dh = (float4*)sWhi;
        float4* dl = (float4*)sWlo;
        for (int i = tid; i < NOUT * LD / 8; i += 256) { dh[i] = srch[i]; dl[i] = srcl[i]; }
    }
    // load + hi/lo split A
    for (int p = tid; p < 128 * (K / 2); p += 256) {
        int r = p / (K / 2), cp = p % (K / 2);
        int gr = row0 + r;
        float2 v = (gr < n) ? *(const float2*)&X[(size_t)gr * K + 2 * cp]
                            : make_float2(0.f, 0.f);
        __nv_bfloat16 h0 = __float2bfloat16(v.x);
        __nv_bfloat16 h1 = __float2bfloat16(v.y);
        __nv_bfloat16 l0 = __float2bfloat16(v.x - __bfloat162float(h0));
        __nv_bfloat16 l1 = __float2bfloat16(v.y - __bfloat162float(h1));
        __nv_bfloat162 hh; hh.x = h0; hh.y = h1;
        __nv_bfloat162 ll; ll.x = l0; ll.y = l1;
        *(__nv_bfloat162*)&sAhi[r * LD + 2 * cp] = hh;
        *(__nv_bfloat162*)&sAlo[r * LD + 2 * cp] = ll;
    }
    __syncthreads();

    const int warp = tid >> 5, lane = tid & 31;
    const int qr = lane >> 2;           // 0..7
    const int qk = (lane & 3) * 2;      // 0,2,4,6
    const int rA = warp * 16 + qr;

    float acc[NCB][4];
#pragma unroll
    for (int cb = 0; cb < NCB; cb++)
#pragma unroll
        for (int i = 0; i < 4; i++) acc[cb][i] = 0.f;

#pragma unroll
    for (int k0 = 0; k0 < K; k0 += 16) {
        uint32_t ah0 = *(const uint32_t*)&sAhi[rA * LD + k0 + qk];
        uint32_t ah1 = *(const uint32_t*)&sAhi[(rA + 8) * LD + k0 + qk];
        uint32_t ah2 = *(const uint32_t*)&sAhi[rA * LD + k0 + 8 + qk];
        uint32_t ah3 = *(const uint32_t*)&sAhi[(rA + 8) * LD + k0 + 8 + qk];
        uint32_t al0 = *(const uint32_t*)&sAlo[rA * LD + k0 + qk];
        uint32_t al1 = *(const uint32_t*)&sAlo[(rA + 8) * LD + k0 + qk];
        uint32_t al2 = *(const uint32_t*)&sAlo[rA * LD + k0 + 8 + qk];
        uint32_t al3 = *(const uint32_t*)&sAlo[(rA + 8) * LD + k0 + 8 + qk];
#pragma unroll
        for (int cb = 0; cb < NCB; cb++) {
            const __nv_bfloat16* wh = &sWhi[(cb * 8 + qr) * LD + k0 + qk];
            const __nv_bfloat16* wl = &sWlo[(cb * 8 + qr) * LD + k0 + qk];
            uint32_t bh0 = *(const uint32_t*)wh;
            uint32_t bh1 = *(const uint32_t*)(wh + 8);
            uint32_t bl0 = *(const uint32_t*)wl;
            uint32_t bl1 = *(const uint32_t*)(wl + 8);
            mma16816(acc[cb], ah0, ah1, ah2, ah3, bh0, bh1);
            mma16816(acc[cb], ah0, ah1, ah2, ah3, bl0, bl1);
            mma16816(acc[cb], al0, al1, al2, al3, bh0, bh1);
        }
    }

    // epilogue: c0,c1 @ (rtop, col, col+1); c2,c3 @ (rtop+8, col, col+1)
    int rtop = row0 + warp * 16 + qr;
    int rbot = rtop + 8;
    if (MODE == 0) {
        float s0 = (rtop < n) ? __ldg(&sb[rtop]) : 0.f;
        float s1 = (rbot < n) ? __ldg(&sb[rbot]) : 0.f;
#pragma unroll
        for (int cb = 0; cb < NCB; cb++) {
            int c0 = cb * 8 + qk;
            if (rtop < n)
                *(float2*)&out[(size_t)rtop * NOUT + c0] =
                    make_float2(acc[cb][0] * s0, acc[cb][1] * s0);
            if (rbot < n)
                *(float2*)&out[(size_t)rbot * NOUT + c0] =
                    make_float2(acc[cb][2] * s1, acc[cb][3] * s1);
        }
    } else {
#pragma unroll
        for (int cb = 0; cb < NCB; cb++) {
            int c0 = cb * 8 + qk;
            float2 b = *(const float2*)&sb[c0];
            if (rtop < n)
                *(float2*)&out[(size_t)rtop * NOUT + c0] =
                    make_float2(1.f / (1.f + expf(-(acc[cb][0] + b.x))),
                                1.f / (1.f + expf(-(acc[cb][1] + b.y))));
            if (rbot < n)
                *(float2*)&out[(size_t)rbot * NOUT + c0] =
                    make_float2(1.f / (1.f + expf(-(acc[cb][2] + b.x))),
                                1.f / (1.f + expf(-(acc[cb][3] + b.y))));
        }
    }
}

// ---------------- setup: histogram + degrees ----------------
__global__ void hist_init_k(int* counts, float* degl0, float* degl1, int n) {
    int i = blockIdx.x * blockDim.x + threadIdx.x;
    if (i < n) { counts[i] = 0; degl0[i] = 1.f; degl1[i] = 1.f; }
}

__global__ void hist_k(const int* __restrict__ col,
                       const float* __restrict__ ew0, const float* __restrict__ ew1,
                       int* counts, float* degl0, float* degl1, int e) {
    int i = blockIdx.x * blockDim.x + threadIdx.x;
    if (i < e) {
        int c = col[i];
        atomicAdd(&counts[c], 1);
        atomicAdd(&degl0[c], ew0[i]);
        atomicAdd(&degl1[c], ew1[i]);
    }
}

__global__ void dinv_k(const int* __restrict__ counts,
                       const float* __restrict__ degl0, const float* __restrict__ degl1,
                       float* dinva, float* dinvl0, float* dinvl1, int n) {
    int i = blockIdx.x * blockDim.x + threadIdx.x;
    if (i < n) {
        dinva[i]  = rsqrtf(1.f + (float)counts[i]);
        dinvl0[i] = rsqrtf(degl0[i]);
        dinvl1[i] = rsqrtf(degl1[i]);
    }
}

// ---------------- parallel exclusive scan (3 kernels) ----------------
__global__ void scan_partials_k(const int* __restrict__ counts, int* bsum, int n) {
    int i = blockIdx.x * 1024 + threadIdx.x;
    int v = (i < n) ? counts[i] : 0;
#pragma unroll
    for (int o = 16; o > 0; o >>= 1) v += __shfl_xor_sync(0xffffffffu, v, o);
    __shared__ int ws[32];
    if ((threadIdx.x & 31) == 0) ws[threadIdx.x >> 5] = v;
    __syncthreads();
    if (threadIdx.x < 32) {
        int s = ws[threadIdx.x];
#pragma unroll
        for (int o = 16; o > 0; o >>= 1) s += __shfl_xor_sync(0xffffffffu, s, o);
        if (threadIdx.x == 0) bsum[blockIdx.x] = s;
    }
}

__global__ void scan_bsums_k(int* bsum, int* off_last, int nb) {
    if (threadIdx.x == 0) {
        int acc = 0;
        for (int i = 0; i < nb; i++) { int t = bsum[i]; bsum[i] = acc; acc += t; }
        *off_last = acc;
    }
}

__global__ void scan_final_k(const int* __restrict__ counts, const int* __restrict__ bsum,
                             int* off, int* cursor, int n) {
    int i = blockIdx.x * 1024 + threadIdx.x;
    int v = (i < n) ? counts[i] : 0;
    int lane = threadIdx.x & 31, wid = threadIdx.x >> 5;
    int inc = v;
#pragma unroll
    for (int o = 1; o < 32; o <<= 1) {
        int t = __shfl_up_sync(0xffffffffu, inc, o);
        if (lane >= o) inc += t;
    }
    __shared__ int ws[32];
    if (lane == 31) ws[wid] = inc;
    __syncthreads();
    if (wid == 0) {
        int s = ws[lane];
        int si = s;
#pragma unroll
        for (int o = 1; o < 32; o <<= 1) {
            int t = __shfl_up_sync(0xffffffffu, si, o);
            if (lane >= o) si += t;
        }
        ws[lane] = si - s;
    }
    __syncthreads();
    int excl = inc - v + ws[wid] + bsum[blockIdx.x];
    if (i < n) { off[i] = excl; cursor[i] = excl; }
}

__global__ void csr_scatter_k(const int* __restrict__ row, const int* __restrict__ col,
                              const float* __restrict__ ew0, const float* __restrict__ ew1,
                              int* cursor, int* csr_src, float* csr_w0, float* csr_w1, int e) {
    int i = blockIdx.x * blockDim.x + threadIdx.x;
    if (i < e) {
        int c = col[i];
        int p = atomicAdd(&cursor[c], 1);
        csr_src[p] = row[i];
        csr_w0[p] = ew0[i];
        csr_w1[p] = ew1[i];
    }
}

// ---------------- fused gather + attention: warp per node ----------------
__global__ void gather_fuse_k(const float4* __restrict__ xwa, const float4* __restrict__ xwl,
                              const int* __restrict__ off, const int* __restrict__ csr_src,
                              const float* __restrict__ csr_w,
                              const float* __restrict__ dinva, const float* __restrict__ dinvl,
                              const float* __restrict__ b_adj, const float* __restrict__ b_lab,
                              const float* __restrict__ ap1, const float* __restrict__ apb1,
                              const float* __restrict__ ap2,
                              float4* __restrict__ xout, int do_relu, int n) {
    __shared__ float s_ap1t[ATT * HIDD];
    __shared__ float s_b[ATT], s_a2[ATT];
    for (int idx = threadIdx.x; idx < ATT * HIDD; idx += blockDim.x) {
        int j = idx >> 7, k = idx & 127;
        s_ap1t[idx] = ap1[k * ATT + j];
    }
    if (threadIdx.x < ATT) {
        s_b[threadIdx.x]  = apb1[threadIdx.x];
        s_a2[threadIdx.x] = ap2[threadIdx.x];
    }
    __syncthreads();

    int gt = blockIdx.x * blockDim.x + threadIdx.x;
    int node = gt >> 5;
    if (node >= n) return;
    int lane = threadIdx.x & 31;

    float4 acc_a = __ldg(&xwa[node * 32 + lane]);
    float4 acc_l = __ldg(&xwl[node * 32 + lane]);

    int start = __ldg(&off[node]);
    int end   = __ldg(&off[node + 1]);
    int j = start;
    for (; j + 32 <= end; j += 32) {
        int rr0   = __ldg(&csr_src[j + lane]);
        float ww0 = __ldg(&csr_w[j + lane]);
#pragma unroll 8
        for (int i = 0; i < 32; i++) {
            int rr  = __shfl_sync(0xffffffffu, rr0, i);
            float w = __shfl_sync(0xffffffffu, ww0, i);
            float4 va = __ldg(&xwa[rr * 32 + lane]);
            float4 vl = __ldg(&xwl[rr * 32 + lane]);
            acc_a.x += va.x; acc_a.y += va.y; acc_a.z += va.z; acc_a.w += va.w;
            acc_l.x = fmaf(w, vl.x, acc_l.x);
            acc_l.y = fmaf(w, vl.y, acc_l.y);
            acc_l.z = fmaf(w, vl.z, acc_l.z);
            acc_l.w = fmaf(w, vl.w, acc_l.w);
        }
    }
    if (j < end) {
        int m = end - j;
        int rr0   = (lane < m) ? __ldg(&csr_src[j + lane]) : 0;
        float ww0 = (lane < m) ? __ldg(&csr_w[j + lane]) : 0.f;
#pragma unroll 4
        for (int i = 0; i < m; i++) {
            int rr  = __shfl_sync(0xffffffffu, rr0, i);
            float w = __shfl_sync(0xffffffffu, ww0, i);
            float4 va = __ldg(&xwa[rr * 32 + lane]);
            float4 vl = __ldg(&xwl[rr * 32 + lane]);
            acc_a.x += va.x; acc_a.y += va.y; acc_a.z += va.z; acc_a.w += va.w;
            acc_l.x = fmaf(w, vl.x, acc_l.x);
            acc_l.y = fmaf(w, vl.y, acc_l.y);
            acc_l.z = fmaf(w, vl.z, acc_l.z);
            acc_l.w = fmaf(w, vl.w, acc_l.w);
        }
    }

    float da = __ldg(&dinva[node]);
    float dl = __ldg(&dinvl[node]);
    float4 ba4 = __ldg(&((const float4*)b_adj)[lane]);
    float4 bl4 = __ldg(&((const float4*)b_lab)[lane]);
    float z0[4], z1[4];
    z0[0] = fmaf(da, acc_a.x, ba4.x); z0[1] = fmaf(da, acc_a.y, ba4.y);
    z0[2] = fmaf(da, acc_a.z, ba4.z); z0[3] = fmaf(da, acc_a.w, ba4.w);
    z1[0] = fmaf(dl, acc_l.x, bl4.x); z1[1] = fmaf(dl, acc_l.y, bl4.y);
    z1[2] = fmaf(dl, acc_l.z, bl4.z); z1[3] = fmaf(dl, acc_l.w, bl4.w);

    float w0 = 0.f, w1 = 0.f;
    const float4* ap1t4 = (const float4*)s_ap1t;
#pragma unroll
    for (int jj = 0; jj < ATT; jj++) {
        float4 a = ap1t4[jj * 32 + lane];
        float p0 = z0[0] * a.x + z0[1] * a.y + z0[2] * a.z + z0[3] * a.w;
        float p1 = z1[0] * a.x + z1[1] * a.y + z1[2] * a.z + z1[3] * a.w;
#pragma unroll
        for (int o = 16; o > 0; o >>= 1) {
            p0 += __shfl_xor_sync(0xffffffffu, p0, o);
            p1 += __shfl_xor_sync(0xffffffffu, p1, o);
        }
        w0 = fmaf(tanhf(p0 + s_b[jj]), s_a2[jj], w0);
        w1 = fmaf(tanhf(p1 + s_b[jj]), s_a2[jj], w1);
    }
    float beta0 = 1.f / (1.f + expf(w1 - w0));
    float beta1 = 1.f - beta0;

    float4 o4;
    o4.x = beta0 * z0[0] + beta1 * z1[0];
    o4.y = beta0 * z0[1] + beta1 * z1[1];
    o4.z = beta0 * z0[2] + beta1 * z1[2];
    o4.w = beta0 * z0[3] + beta1 * z1[3];
    if (do_relu) {
        o4.x = fmaxf(o4.x, 0.f); o4.y = fmaxf(o4.y, 0.f);
        o4.z = fmaxf(o4.z, 0.f); o4.w = fmaxf(o4.w, 0.f);
    }
    xout[node * 32 + lane] = o4;
}

// ---------------- host orchestration ----------------
extern "C" void kernel_launch(void* const* d_in, const int* in_sizes, int n_in,
                              void* d_out, int out_size) {
    const float* x_in  = (const float*)d_in[0];
    const float* y_in  = (const float*)d_in[1];
    const int*   row   = (const int*)d_in[2];
    const int*   col   = (const int*)d_in[3];
    const float* ews   = (const float*)d_in[4];
    const float* W0    = (const float*)d_in[5];
    const float* b0    = (const float*)d_in[6];
    const float* W1    = (const float*)d_in[7];
    const float* b1    = (const float*)d_in[8];
    const float* Wl    = (const float*)d_in[9];
    const float* bl    = (const float*)d_in[10];
    const float* ap1   = (const float*)d_in[11];
    const float* apb1  = (const float*)d_in[12];
    const float* ap2   = (const float*)d_in[13];
    const float* mW    = (const float*)d_in[14];
    const float* mb    = (const float*)d_in[15];
    float* out = (float*)d_out;

    float *xw_a, *xw_l, *xbuf, *ybuf;
    float *dinva, *dinvl0, *dinvl1, *degl0, *degl1, *csr_w0, *csr_w1;
    int *counts, *off, *cursor, *csr_src, *bsum;
    __nv_bfloat16 *w0hi, *w0lo, *w1hi, *w1lo, *wlhi, *wllo, *mwhi, *mwlo;
    cudaGetSymbolAddress((void**)&xw_a,   g_xw_a);
    cudaGetSymbolAddress((void**)&xw_l,   g_xw_l);
    cudaGetSymbolAddress((void**)&xbuf,   g_xbuf);
    cudaGetSymbolAddress((void**)&ybuf,   g_ybuf);
    cudaGetSymbolAddress((void**)&counts, g_counts);
    cudaGetSymbolAddress((void**)&off,    g_off);
    cudaGetSymbolAddress((void**)&cursor, g_cursor);
    cudaGetSymbolAddress((void**)&bsum,   g_bsum);
    cudaGetSymbolAddress((void**)&csr_src, g_csr_src);
    cudaGetSymbolAddress((void**)&csr_w0, g_csr_w0);
    cudaGetSymbolAddress((void**)&csr_w1, g_csr_w1);
    cudaGetSymbolAddress((void**)&dinva,  g_dinva);
    cudaGetSymbolAddress((void**)&dinvl0, g_dinvl0);
    cudaGetSymbolAddress((void**)&dinvl1, g_dinvl1);
    cudaGetSymbolAddress((void**)&degl0,  g_degl0);
    cudaGetSymbolAddress((void**)&degl1,  g_degl1);
    cudaGetSymbolAddress((void**)&w0hi,   g_w0hi);
    cudaGetSymbolAddress((void**)&w0lo,   g_w0lo);
    cudaGetSymbolAddress((void**)&w1hi,   g_w1hi);
    cudaGetSymbolAddress((void**)&w1lo,   g_w1lo);
    cudaGetSymbolAddress((void**)&wlhi,   g_wlhi);
    cudaGetSymbolAddress((void**)&wllo,   g_wllo);
    cudaGetSymbolAddress((void**)&mwhi,   g_mwhi);
    cudaGetSymbolAddress((void**)&mwlo,   g_mwlo);

    const float* ew0 = ews;
    const float* ew1 = ews + EE;

    const int n_blocks   = (NN + 255) / 256;
    const int e_blocks   = (EE + 255) / 256;
    const int scan_blk   = (NN + 1023) / 1024;
    const int mma_blk    = (NN + 127) / 128;        // 391
    const int gf_blocks  = (NN * 32 + 255) / 256;

    // dynamic smem sizes (bf16 elements * 2 bytes)
    const int SM_CONV128 = (2 * 128 * (HIDD + 8) + 2 * HIDD * (HIDD + 8)) * 2;  // 139264
    const int SM_CONV64  = (2 * 128 * (CLSS + 8) + 2 * HIDD * (CLSS + 8)) * 2;  // 73728
    const int SM_YG      = (2 * 128 * (HIDD + 8) + 2 * CLSS * (HIDD + 8)) * 2;  // 104448
    cudaFuncSetAttribute(mma_gemm<HIDD, HIDD, 0>, cudaFuncAttributeMaxDynamicSharedMemorySize, SM_CONV128);
    cudaFuncSetAttribute(mma_gemm<CLSS, HIDD, 0>, cudaFuncAttributeMaxDynamicSharedMemorySize, SM_CONV64);
    cudaFuncSetAttribute(mma_gemm<HIDD, CLSS, 1>, cudaFuncAttributeMaxDynamicSharedMemorySize, SM_YG);

    // ---- setup: weight split/transpose + CSR build ----
    wsplit_k<<<(HIDD * HIDD + 255) / 256, 256>>>(W0, w0hi, w0lo, HIDD, HIDD);
    wsplit_k<<<(HIDD * HIDD + 255) / 256, 256>>>(W1, w1hi, w1lo, HIDD, HIDD);
    wsplit_k<<<(CLSS * HIDD + 255) / 256, 256>>>(Wl, wlhi, wllo, CLSS, HIDD);
    wsplit_k<<<(HIDD * CLSS + 255) / 256, 256>>>(mW, mwhi, mwlo, HIDD, CLSS);
    hist_init_k<<<n_blocks, 256>>>(counts, degl0, degl1, NN);
    hist_k<<<e_blocks, 256>>>(col, ew0, ew1, counts, degl0, degl1, EE);
    dinv_k<<<n_blocks, 256>>>(counts, degl0, degl1, dinva, dinvl0, dinvl1, NN);
    scan_partials_k<<<scan_blk, 1024>>>(counts, bsum, NN);
    scan_bsums_k<<<1, 32>>>(bsum, off + NN, scan_blk);
    scan_final_k<<<scan_blk, 1024>>>(counts, bsum, off, cursor, NN);
    csr_scatter_k<<<e_blocks, 256>>>(row, col, ew0, ew1, cursor,
                                     csr_src, csr_w0, csr_w1, EE);

    const __nv_bfloat16* convWhi[2] = {w0hi, w1hi};
    const __nv_bfloat16* convWlo[2] = {w0lo, w1lo};
    const float* convB[2] = {b0, b1};
    const float* dinvl[2] = {dinvl0, dinvl1};
    const float* csrw[2]  = {csr_w0, csr_w1};

    for (int layer = 0; layer < 2; layer++) {
        const float* Xin = (layer == 0) ? x_in : xbuf;
        const float* Yin = (layer == 0) ? y_in : ybuf;
        int last = (layer == 1);
        float* xout = last ? out : xbuf;
        float* yout = last ? (out + (size_t)NN * HIDD) : ybuf;

        mma_gemm<HIDD, HIDD, 0><<<mma_blk, 256, SM_CONV128>>>(
            Xin, convWhi[layer], convWlo[layer], dinva, xw_a, NN);
        mma_gemm<CLSS, HIDD, 0><<<mma_blk, 256, SM_CONV64>>>(
            Yin, wlhi, wllo, dinvl[layer], xw_l, NN);

        gather_fuse_k<<<gf_blocks, 256>>>((const float4*)xw_a, (const float4*)xw_l,
                                          off, csr_src, csrw[layer],
                                          dinva, dinvl[layer],
                                          convB[layer], bl, ap1, apb1, ap2,
                                          (float4*)xout, last ? 0 : 1, NN);

        mma_gemm<HIDD, CLSS, 1><<<mma_blk, 256, SM_YG>>>(
            xout, mwhi, mwlo, mb, yout, NN);
    }
}